// round 9
// baseline (speedup 1.0000x reference)
#include <cuda_runtime.h>
#include <math_constants.h>

#define N_NODES 50000
#define N_EDGES 600000
#define REL_NUM 500
#define E_HID 128

// ---------------- device scratch (no allocation allowed) ----------------
__device__ float    g_remb[REL_NUM * E_HID];   // ww(rel_emb): 256 KB
__device__ float    g_dp[N_EDGES];             // per-edge logits: 2.4 MB
__device__ unsigned g_max_u;                   // ordered-uint encoding of max
__device__ float    g_sumexp;
__device__ int      g_cnt[N_NODES + 1];        // histogram -> CSR offsets
__device__ int      g_cur[N_NODES];            // insertion cursors
__device__ int      g_eord[N_EDGES];           // edge ids grouped by dst

__device__ __forceinline__ unsigned f2u_ord(float f) {
    unsigned u = __float_as_uint(f);
    return (u & 0x80000000u) ? ~u : (u | 0x80000000u);
}
__device__ __forceinline__ float u2f_ord(unsigned u) {
    unsigned b = (u & 0x80000000u) ? (u & 0x7FFFFFFFu) : ~u;
    return __uint_as_float(b);
}

// ---------------- kernels ----------------

// zero counters + softmax scalars
__global__ void k_zero() {
    int i = blockIdx.x * blockDim.x + threadIdx.x;
    if (i <= N_NODES) g_cnt[i] = 0;
    if (i == 0) { g_max_u = 0u; g_sumexp = 0.0f; }
}

// r_emb = rel_emb @ ww_w^T (into g_remb), rel_out = rel_emb @ rel_w^T (into out)
__global__ void k_relgemm(const float* __restrict__ rel_emb,
                          const float* __restrict__ ww_w,
                          const float* __restrict__ rel_w,
                          float* __restrict__ rel_out) {
    __shared__ float row[E_HID];
    int r = blockIdx.x;
    int t = threadIdx.x;
    row[t] = rel_emb[r * E_HID + t];
    __syncthreads();
    const float* w1 = ww_w + t * E_HID;
    const float* w2 = rel_w + t * E_HID;
    float s1 = 0.f, s2 = 0.f;
#pragma unroll 8
    for (int k = 0; k < E_HID; ++k) {
        float rv = row[k];
        s1 = fmaf(rv, w1[k], s1);
        s2 = fmaf(rv, w2[k], s2);
    }
    g_remb[r * E_HID + t]  = s1;
    rel_out[r * E_HID + t] = s2;
}

// per-edge logit + global max + dst histogram; 2-way unrolled for MLP
__global__ void k_edgedot(const float4* __restrict__ x4,
                          const int* __restrict__ eidx,
                          const int* __restrict__ etype) {
    const float4* remb4 = (const float4*)g_remb;
    int lane   = threadIdx.x & 31;
    int warp   = (blockIdx.x * blockDim.x + threadIdx.x) >> 5;
    int nwarps = (gridDim.x * blockDim.x) >> 5;

    float lmax = -CUDART_INF_F;
    for (int e = warp; e < N_EDGES; e += 2 * nwarps) {
        int eB = e + nwarps;
        bool hasB = (eB < N_EDGES);
        int sA = eidx[e], dA = eidx[N_EDGES + e], tA = etype[e];
        int sB = 0, dB = 0, tB = 0;
        if (hasB) { sB = eidx[eB]; dB = eidx[N_EDGES + eB]; tB = etype[eB]; }

        float4 xsA = x4[sA * 32 + lane];
        float4 xdA = x4[dA * 32 + lane];
        float4 reA = remb4[tA * 32 + lane];
        float4 xsB, xdB, reB;
        if (hasB) {
            xsB = x4[sB * 32 + lane];
            xdB = x4[dB * 32 + lane];
            reB = remb4[tB * 32 + lane];
        }

        float vA = (xsA.x + reA.x) * xdA.x;
        vA = fmaf(xsA.y + reA.y, xdA.y, vA);
        vA = fmaf(xsA.z + reA.z, xdA.z, vA);
        vA = fmaf(xsA.w + reA.w, xdA.w, vA);
#pragma unroll
        for (int o = 16; o; o >>= 1) vA += __shfl_xor_sync(0xffffffffu, vA, o);
        if (lane == 0) {
            g_dp[e] = vA;
            atomicAdd(&g_cnt[dA + 1], 1);
        }
        lmax = fmaxf(lmax, vA);

        if (hasB) {
            float vB = (xsB.x + reB.x) * xdB.x;
            vB = fmaf(xsB.y + reB.y, xdB.y, vB);
            vB = fmaf(xsB.z + reB.z, xdB.z, vB);
            vB = fmaf(xsB.w + reB.w, xdB.w, vB);
#pragma unroll
            for (int o = 16; o; o >>= 1) vB += __shfl_xor_sync(0xffffffffu, vB, o);
            if (lane == 0) {
                g_dp[eB] = vB;
                atomicAdd(&g_cnt[dB + 1], 1);
            }
            lmax = fmaxf(lmax, vB);
        }
    }
    __shared__ unsigned smax;
    if (threadIdx.x == 0) smax = 0u;
    __syncthreads();
    if (lane == 0) atomicMax(&smax, f2u_ord(lmax));
    __syncthreads();
    if (threadIdx.x == 0) atomicMax(&g_max_u, smax);
}

// single-block inclusive scan over g_cnt[0..N_NODES] -> CSR offsets + cursors
__global__ void k_scan() {
    __shared__ int wsum[32];
    __shared__ int sh_carry;
    int tid = threadIdx.x;
    int lane = tid & 31, wid = tid >> 5;
    if (tid == 0) sh_carry = 0;
    __syncthreads();

    for (int base = 0; base <= N_NODES; base += 1024) {
        int i = base + tid;
        int v = (i <= N_NODES) ? g_cnt[i] : 0;
        // warp inclusive scan
        int sv = v;
#pragma unroll
        for (int o = 1; o < 32; o <<= 1) {
            int n = __shfl_up_sync(0xffffffffu, sv, o);
            if (lane >= o) sv += n;
        }
        if (lane == 31) wsum[wid] = sv;
        __syncthreads();
        if (wid == 0) {
            int w = wsum[lane];
#pragma unroll
            for (int o = 1; o < 32; o <<= 1) {
                int n = __shfl_up_sync(0xffffffffu, w, o);
                if (lane >= o) w += n;
            }
            wsum[lane] = w;
        }
        __syncthreads();
        int incl = sv + (wid > 0 ? wsum[wid - 1] : 0);
        int total = wsum[31];
        int res = incl + sh_carry;
        if (i <= N_NODES) {
            g_cnt[i] = res;
            if (i < N_NODES) g_cur[i] = res;
        }
        __syncthreads();
        if (tid == 0) sh_carry += total;
        __syncthreads();
    }
}

// permute edges into CSR order + sum exp(dp-max) + res_att passthrough
__global__ void k_permute(const int* __restrict__ eidx,
                          const float* __restrict__ res_att,
                          float* __restrict__ out) {
    const int RES_OFF = N_NODES * E_HID + REL_NUM * E_HID;
    float mx = u2f_ord(g_max_u);
    float s = 0.f;
    for (int e = blockIdx.x * blockDim.x + threadIdx.x; e < N_EDGES;
         e += gridDim.x * blockDim.x) {
        int d = eidx[N_EDGES + e];
        int pos = atomicAdd(&g_cur[d], 1);
        g_eord[pos] = e;
        s += __expf(g_dp[e] - mx);
        out[RES_OFF + e] = res_att[e];
    }
#pragma unroll
    for (int o = 16; o; o >>= 1) s += __shfl_xor_sync(0xffffffffu, s, o);
    __shared__ float ssum[32];
    int lane = threadIdx.x & 31, wid = threadIdx.x >> 5;
    if (lane == 0) ssum[wid] = s;
    __syncthreads();
    if (threadIdx.x == 0) {
        float t = 0.f;
        int nw = blockDim.x >> 5;
        for (int i = 0; i < nw; ++i) t += ssum[i];
        atomicAdd(&g_sumexp, t);
    }
}

// warp-per-node gather: out[n] = relu( sum_e attn[e] * (x[src]+remb[type]) )
__global__ void k_gather(const float4* __restrict__ x4,
                         const int* __restrict__ eidx,
                         const int* __restrict__ etype,
                         float* __restrict__ out) {
    const float4* remb4 = (const float4*)g_remb;
    float mx  = u2f_ord(g_max_u);
    float inv = 1.0f / g_sumexp;
    int lane   = threadIdx.x & 31;
    int warp   = (blockIdx.x * blockDim.x + threadIdx.x) >> 5;
    int nwarps = (gridDim.x * blockDim.x) >> 5;

    for (int n = warp; n < N_NODES; n += nwarps) {
        int beg = g_cnt[n], end = g_cnt[n + 1];
        float ax = 0.f, ay = 0.f, az = 0.f, aw = 0.f;
        for (int i = beg; i < end; ++i) {
            int e = g_eord[i];
            int s = eidx[e];
            int t = etype[e];
            float a = __expf(g_dp[e] - mx) * inv;
            float4 xs = x4[s * 32 + lane];
            float4 re = remb4[t * 32 + lane];
            ax = fmaf(xs.x + re.x, a, ax);
            ay = fmaf(xs.y + re.y, a, ay);
            az = fmaf(xs.z + re.z, a, az);
            aw = fmaf(xs.w + re.w, a, aw);
        }
        float4 r;
        r.x = fmaxf(ax, 0.f); r.y = fmaxf(ay, 0.f);
        r.z = fmaxf(az, 0.f); r.w = fmaxf(aw, 0.f);
        ((float4*)out)[n * 32 + lane] = r;
    }
}

// ---------------- launch ----------------
extern "C" void kernel_launch(void* const* d_in, const int* in_sizes, int n_in,
                              void* d_out, int out_size) {
    const float* x       = (const float*)d_in[0];
    const int*   eidx    = (const int*)d_in[1];
    const int*   etype   = (const int*)d_in[2];
    const float* rel_emb = (const float*)d_in[3];
    const float* res_att = (const float*)d_in[4];
    const float* ww_w    = (const float*)d_in[5];
    const float* rel_w   = (const float*)d_in[6];
    float* out = (float*)d_out;

    const float4* x4 = (const float4*)x;

    k_zero<<<(N_NODES + 256) / 256, 256>>>();
    k_relgemm<<<REL_NUM, E_HID>>>(rel_emb, ww_w, rel_w, out + N_NODES * E_HID);
    k_edgedot<<<2368, 256>>>(x4, eidx, etype);
    k_scan<<<1, 1024>>>();
    k_permute<<<1184, 256>>>(eidx, res_att, out);
    k_gather<<<6250, 256>>>(x4, eidx, etype, out);
}

// round 11
// speedup vs baseline: 1.1736x; 1.1736x over previous
#include <cuda_runtime.h>
#include <math_constants.h>

#define N_NODES 50000
#define N_EDGES 600000
#define REL_NUM 500
#define E_HID 128

#define SCAN_N   (N_NODES + 1)          // 50001
#define SCAN_B   1024
#define SCAN_NB  ((SCAN_N + SCAN_B - 1) / SCAN_B)   // 49

// ---------------- device scratch (no allocation allowed) ----------------
__device__ float    g_remb[REL_NUM * E_HID];   // ww(rel_emb): 256 KB
__device__ float    g_dp[N_EDGES];             // per-edge logits
__device__ unsigned g_max_u;                   // ordered-uint encoding of max
__device__ float    g_sumexp;
__device__ int      g_cnt[SCAN_N];             // histogram -> CSR offsets
__device__ int      g_cur[N_NODES];            // insertion cursors
__device__ int      g_bsum[SCAN_NB];           // scan block partials
__device__ float    g_att[N_EDGES];            // exp(dp-mx) in CSR order
__device__ int2     g_st[N_EDGES];             // (src,type) in CSR order

__device__ __forceinline__ unsigned f2u_ord(float f) {
    unsigned u = __float_as_uint(f);
    return (u & 0x80000000u) ? ~u : (u | 0x80000000u);
}
__device__ __forceinline__ float u2f_ord(unsigned u) {
    unsigned b = (u & 0x80000000u) ? (u & 0x7FFFFFFFu) : ~u;
    return __uint_as_float(b);
}

// ---------------- kernels ----------------

__global__ void k_zero() {
    int i = blockIdx.x * blockDim.x + threadIdx.x;
    if (i < SCAN_N) g_cnt[i] = 0;
    if (i == 0) { g_max_u = 0u; g_sumexp = 0.0f; }
}

// r_emb = rel_emb @ ww_w^T (into g_remb), rel_out = rel_emb @ rel_w^T (into out)
__global__ void k_relgemm(const float* __restrict__ rel_emb,
                          const float* __restrict__ ww_w,
                          const float* __restrict__ rel_w,
                          float* __restrict__ rel_out) {
    __shared__ float row[E_HID];
    int r = blockIdx.x;
    int t = threadIdx.x;
    row[t] = rel_emb[r * E_HID + t];
    __syncthreads();
    const float* w1 = ww_w + t * E_HID;
    const float* w2 = rel_w + t * E_HID;
    float s1 = 0.f, s2 = 0.f;
#pragma unroll 8
    for (int k = 0; k < E_HID; ++k) {
        float rv = row[k];
        s1 = fmaf(rv, w1[k], s1);
        s2 = fmaf(rv, w2[k], s2);
    }
    g_remb[r * E_HID + t]  = s1;
    rel_out[r * E_HID + t] = s2;
}

// per-edge logit + global max + dst histogram; 2-way unrolled for MLP
__global__ void k_edgedot(const float4* __restrict__ x4,
                          const int* __restrict__ eidx,
                          const int* __restrict__ etype) {
    const float4* remb4 = (const float4*)g_remb;
    int lane   = threadIdx.x & 31;
    int warp   = (blockIdx.x * blockDim.x + threadIdx.x) >> 5;
    int nwarps = (gridDim.x * blockDim.x) >> 5;

    float lmax = -CUDART_INF_F;
    for (int e = warp; e < N_EDGES; e += 2 * nwarps) {
        int eB = e + nwarps;
        bool hasB = (eB < N_EDGES);
        int sA = eidx[e], dA = eidx[N_EDGES + e], tA = etype[e];
        int sB = 0, dB = 0, tB = 0;
        if (hasB) { sB = eidx[eB]; dB = eidx[N_EDGES + eB]; tB = etype[eB]; }

        float4 xsA = x4[sA * 32 + lane];
        float4 xdA = x4[dA * 32 + lane];
        float4 reA = remb4[tA * 32 + lane];
        float4 xsB, xdB, reB;
        if (hasB) {
            xsB = x4[sB * 32 + lane];
            xdB = x4[dB * 32 + lane];
            reB = remb4[tB * 32 + lane];
        }

        float vA = (xsA.x + reA.x) * xdA.x;
        vA = fmaf(xsA.y + reA.y, xdA.y, vA);
        vA = fmaf(xsA.z + reA.z, xdA.z, vA);
        vA = fmaf(xsA.w + reA.w, xdA.w, vA);
#pragma unroll
        for (int o = 16; o; o >>= 1) vA += __shfl_xor_sync(0xffffffffu, vA, o);
        if (lane == 0) {
            g_dp[e] = vA;
            atomicAdd(&g_cnt[dA + 1], 1);
        }
        lmax = fmaxf(lmax, vA);

        if (hasB) {
            float vB = (xsB.x + reB.x) * xdB.x;
            vB = fmaf(xsB.y + reB.y, xdB.y, vB);
            vB = fmaf(xsB.z + reB.z, xdB.z, vB);
            vB = fmaf(xsB.w + reB.w, xdB.w, vB);
#pragma unroll
            for (int o = 16; o; o >>= 1) vB += __shfl_xor_sync(0xffffffffu, vB, o);
            if (lane == 0) {
                g_dp[eB] = vB;
                atomicAdd(&g_cnt[dB + 1], 1);
            }
            lmax = fmaxf(lmax, vB);
        }
    }
    __shared__ unsigned smax;
    if (threadIdx.x == 0) smax = 0u;
    __syncthreads();
    if (lane == 0) atomicMax(&smax, f2u_ord(lmax));
    __syncthreads();
    if (threadIdx.x == 0) atomicMax(&g_max_u, smax);
}

// ---- 2-level scan over g_cnt[0..N_NODES] ----
// stage 1: per-block inclusive scan (in place) + block totals
__global__ void k_scan1() {
    __shared__ int wsum[32];
    int tid = threadIdx.x, lane = tid & 31, wid = tid >> 5;
    int i = blockIdx.x * SCAN_B + tid;
    int v = (i < SCAN_N) ? g_cnt[i] : 0;
    int sv = v;
#pragma unroll
    for (int o = 1; o < 32; o <<= 1) {
        int n = __shfl_up_sync(0xffffffffu, sv, o);
        if (lane >= o) sv += n;
    }
    if (lane == 31) wsum[wid] = sv;
    __syncthreads();
    if (wid == 0) {
        int w = wsum[lane];
#pragma unroll
        for (int o = 1; o < 32; o <<= 1) {
            int n = __shfl_up_sync(0xffffffffu, w, o);
            if (lane >= o) w += n;
        }
        wsum[lane] = w;
    }
    __syncthreads();
    int incl = sv + (wid > 0 ? wsum[wid - 1] : 0);
    if (i < SCAN_N) g_cnt[i] = incl;
    if (tid == SCAN_B - 1) g_bsum[blockIdx.x] = incl;
}

// stage 2: scan the 49 block totals (single block, 64 threads)
__global__ void k_scan2() {
    __shared__ int w0;
    int tid = threadIdx.x, lane = tid & 31, wid = tid >> 5;
    int v = (tid < SCAN_NB) ? g_bsum[tid] : 0;
    int sv = v;
#pragma unroll
    for (int o = 1; o < 32; o <<= 1) {
        int n = __shfl_up_sync(0xffffffffu, sv, o);
        if (lane >= o) sv += n;
    }
    if (tid == 31) w0 = sv;
    __syncthreads();
    if (wid == 1) sv += w0;
    if (tid < SCAN_NB) g_bsum[tid] = sv;
}

// stage 3: add block offsets; copy to cursors
__global__ void k_scan3() {
    int b = blockIdx.x;
    int i = b * SCAN_B + threadIdx.x;
    if (i < SCAN_N) {
        int off = (b > 0) ? g_bsum[b - 1] : 0;
        int v = g_cnt[i] + off;
        g_cnt[i] = v;
        if (i < N_NODES) g_cur[i] = v;
    }
}

// permute edges into CSR order (store exp + (src,type) payloads),
// sum exp(dp-max), res_att passthrough
__global__ void k_permute(const int* __restrict__ eidx,
                          const int* __restrict__ etype,
                          const float* __restrict__ res_att,
                          float* __restrict__ out) {
    const int RES_OFF = N_NODES * E_HID + REL_NUM * E_HID;
    float mx = u2f_ord(g_max_u);
    float s = 0.f;
    for (int e = blockIdx.x * blockDim.x + threadIdx.x; e < N_EDGES;
         e += gridDim.x * blockDim.x) {
        int d = eidx[N_EDGES + e];
        int pos = atomicAdd(&g_cur[d], 1);
        float a = __expf(g_dp[e] - mx);
        g_att[pos] = a;
        g_st[pos] = make_int2(eidx[e], etype[e]);
        s += a;
        out[RES_OFF + e] = res_att[e];
    }
#pragma unroll
    for (int o = 16; o; o >>= 1) s += __shfl_xor_sync(0xffffffffu, s, o);
    __shared__ float ssum[32];
    int lane = threadIdx.x & 31, wid = threadIdx.x >> 5;
    if (lane == 0) ssum[wid] = s;
    __syncthreads();
    if (threadIdx.x == 0) {
        float t = 0.f;
        int nw = blockDim.x >> 5;
        for (int i = 0; i < nw; ++i) t += ssum[i];
        atomicAdd(&g_sumexp, t);
    }
}

// warp-per-node gather: out[n] = relu( sum_e att[e]/Z * (x[src]+remb[type]) )
__global__ void k_gather(const float4* __restrict__ x4,
                         float* __restrict__ out) {
    const float4* remb4 = (const float4*)g_remb;
    float inv = 1.0f / g_sumexp;
    int lane   = threadIdx.x & 31;
    int warp   = (blockIdx.x * blockDim.x + threadIdx.x) >> 5;
    int nwarps = (gridDim.x * blockDim.x) >> 5;

    for (int n = warp; n < N_NODES; n += nwarps) {
        int beg = g_cnt[n], end = g_cnt[n + 1];
        float ax = 0.f, ay = 0.f, az = 0.f, aw = 0.f;
        for (int i = beg; i < end; ++i) {
            int2 st = g_st[i];
            float a = g_att[i];
            float4 xs = x4[st.x * 32 + lane];
            float4 re = remb4[st.y * 32 + lane];
            ax = fmaf(xs.x + re.x, a, ax);
            ay = fmaf(xs.y + re.y, a, ay);
            az = fmaf(xs.z + re.z, a, az);
            aw = fmaf(xs.w + re.w, a, aw);
        }
        float4 r;
        r.x = fmaxf(ax * inv, 0.f); r.y = fmaxf(ay * inv, 0.f);
        r.z = fmaxf(az * inv, 0.f); r.w = fmaxf(aw * inv, 0.f);
        ((float4*)out)[n * 32 + lane] = r;
    }
}

// ---------------- launch ----------------
extern "C" void kernel_launch(void* const* d_in, const int* in_sizes, int n_in,
                              void* d_out, int out_size) {
    const float* x       = (const float*)d_in[0];
    const int*   eidx    = (const int*)d_in[1];
    const int*   etype   = (const int*)d_in[2];
    const float* rel_emb = (const float*)d_in[3];
    const float* res_att = (const float*)d_in[4];
    const float* ww_w    = (const float*)d_in[5];
    const float* rel_w   = (const float*)d_in[6];
    float* out = (float*)d_out;

    const float4* x4 = (const float4*)x;

    k_zero<<<(SCAN_N + 255) / 256, 256>>>();
    k_relgemm<<<REL_NUM, E_HID>>>(rel_emb, ww_w, rel_w, out + N_NODES * E_HID);
    k_edgedot<<<2368, 256>>>(x4, eidx, etype);
    k_scan1<<<SCAN_NB, SCAN_B>>>();
    k_scan2<<<1, 64>>>();
    k_scan3<<<SCAN_NB, SCAN_B>>>();
    k_permute<<<1184, 256>>>(eidx, etype, res_att, out);
    k_gather<<<6250, 256>>>(x4, out);
}